// round 4
// baseline (speedup 1.0000x reference)
#include <cuda_runtime.h>
#include <cstdint>

#define D_IN  128
#define D_HID 48
#define D_OUT 32
#define MAX_N 100000
#define MAX_E 1600000

// Scratch (module-static device memory; device-global scratch is the
// sanctioned no-alloc pattern)
__device__ float s_h1  [MAX_N * D_HID];
__device__ float s_agg1[MAX_N * D_HID];
__device__ float s_h2  [MAX_N * D_OUT];
__device__ float s_agg2[MAX_N * D_OUT];
__device__ float s_deg [MAX_N];
__device__ int   s_src [MAX_E];
__device__ int   s_dst [MAX_E];
__device__ float s_norm[MAX_E];
__device__ int   s_flag[1];              // 1 => edge_index delivered as int64

// ---------------------------------------------------------------------------
// Detect edge_index dtype: if int64 (values < 2^32), all odd 32-bit words are 0.
// ---------------------------------------------------------------------------
__global__ void gcn_detect(const unsigned* __restrict__ ei_words,
                           int* __restrict__ flag) {
    if (threadIdx.x == 0 && blockIdx.x == 0) {
        int nz = 0;
        #pragma unroll 8
        for (int i = 1; i < 512; i += 2) nz += (ei_words[i] != 0u);
        flag[0] = (nz == 0) ? 1 : 0;
    }
}

// ---------------------------------------------------------------------------
// zero scratch + convert indices to clamped int32 (dtype chosen by flag)
// ---------------------------------------------------------------------------
__global__ void gcn_prep(const void* __restrict__ ei_raw,
                         const int* __restrict__ flag,
                         float* __restrict__ agg1, float* __restrict__ agg2,
                         float* __restrict__ deg,
                         int* __restrict__ src32, int* __restrict__ dst32,
                         int n, int E) {
    int stride = gridDim.x * blockDim.x;
    int tid0 = blockIdx.x * blockDim.x + threadIdx.x;
    for (int i = tid0; i < n * D_HID; i += stride) {
        agg1[i] = 0.f;
        if (i < n * D_OUT) agg2[i] = 0.f;
        if (i < n)         deg[i]  = 0.f;
    }
    bool is64 = (flag[0] != 0);
    const long long* ei64 = (const long long*)ei_raw;
    const int*       ei32 = (const int*)ei_raw;
    for (int e = tid0; e < E; e += stride) {
        int sv, dv;
        if (is64) {
            sv = (int)ei64[e];
            dv = (int)ei64[E + e];
        } else {
            sv = ei32[e];
            dv = ei32[E + e];
        }
        // clamp: converts any misparse into rel_err instead of an addr-space trap
        sv = min(max(sv, 0), n - 1);
        dv = min(max(dv, 0), n - 1);
        src32[e] = sv;
        dst32[e] = dv;
    }
}

// ---------------------------------------------------------------------------
// degree = segment_sum(ew over dst); dinv = rsqrt(deg+1)
// ---------------------------------------------------------------------------
__global__ void gcn_deg(const int* __restrict__ dst32,
                        const float* __restrict__ ew,
                        float* __restrict__ deg, int E) {
    int e = blockIdx.x * blockDim.x + threadIdx.x;
    if (e < E) atomicAdd(deg + dst32[e], ew[e]);
}

__global__ void gcn_dinv(float* __restrict__ deg, int n) {
    int i = blockIdx.x * blockDim.x + threadIdx.x;
    if (i < n) deg[i] = rsqrtf(deg[i] + 1.0f);   // self-loop weight 1
}

__global__ void gcn_norm(const int* __restrict__ src32,
                         const int* __restrict__ dst32,
                         const float* __restrict__ ew,
                         const float* __restrict__ dinv,
                         float* __restrict__ norm, int E) {
    int e = blockIdx.x * blockDim.x + threadIdx.x;
    if (e < E) norm[e] = dinv[src32[e]] * ew[e] * dinv[dst32[e]];
}

// ---------------------------------------------------------------------------
// K-tiled fp32 GEMM: H[n, DOUT] = X[n, DIN] @ W[DIN, DOUT]
// ---------------------------------------------------------------------------
template<int DIN, int DOUT, int BM, int BK, int TM, int TN>
__global__ void gcn_gemm(const float* __restrict__ X,
                         const float* __restrict__ W,
                         float* __restrict__ H, int n) {
    constexpr int RT = BM / TM;
    constexpr int CT = DOUT / TN;
    constexpr int NT = RT * CT;

    __shared__ float sXT[BK * (BM + 1)];   // transposed, padded
    __shared__ float sW [BK * DOUT];

    int tid  = threadIdx.x;
    int row0 = blockIdx.x * BM;
    int ti = tid / CT;
    int tj = tid % CT;

    float acc[TM][TN];
    #pragma unroll
    for (int i = 0; i < TM; i++)
        #pragma unroll
        for (int j = 0; j < TN; j++) acc[i][j] = 0.f;

    for (int k0 = 0; k0 < DIN; k0 += BK) {
        for (int i = tid; i < BM * BK; i += NT) {
            int r = i / BK, c = i % BK;
            float v = (row0 + r < n) ? X[(size_t)(row0 + r) * DIN + k0 + c] : 0.f;
            sXT[c * (BM + 1) + r] = v;
        }
        for (int i = tid; i < BK * DOUT; i += NT) {
            int kk = i / DOUT, c = i % DOUT;
            sW[kk * DOUT + c] = W[(size_t)(k0 + kk) * DOUT + c];
        }
        __syncthreads();

        #pragma unroll 4
        for (int kk = 0; kk < BK; kk++) {
            float xr[TM];
            #pragma unroll
            for (int i = 0; i < TM; i++) xr[i] = sXT[kk * (BM + 1) + ti * TM + i];
            #pragma unroll
            for (int j = 0; j < TN; j++) {
                float wv = sW[kk * DOUT + tj * TN + j];
                #pragma unroll
                for (int i = 0; i < TM; i++) acc[i][j] += xr[i] * wv;
            }
        }
        __syncthreads();
    }

    #pragma unroll
    for (int i = 0; i < TM; i++) {
        int r = row0 + ti * TM + i;
        if (r < n) {
            #pragma unroll
            for (int j = 0; j < TN; j++)
                H[(size_t)r * DOUT + tj * TN + j] = acc[i][j];
        }
    }
}

// ---------------------------------------------------------------------------
// Edge scatter: agg[dst] += norm[e] * h[src]
// ---------------------------------------------------------------------------
template<int D>
__global__ void gcn_edge(const int* __restrict__ src32,
                         const int* __restrict__ dst32,
                         const float* __restrict__ norm,
                         const float* __restrict__ h,
                         float* __restrict__ agg, int E) {
    int e = blockIdx.x * blockDim.x + threadIdx.x;
    if (e >= E) return;
    int   s  = src32[e];
    int   d  = dst32[e];
    float nm = norm[e];
    const float* hs = h + (size_t)s * D;
    float*       ad = agg + (size_t)d * D;
    #pragma unroll
    for (int i = 0; i < D; i += 4) {
        float v0 = hs[i + 0], v1 = hs[i + 1], v2 = hs[i + 2], v3 = hs[i + 3];
        atomicAdd(ad + i + 0, v0 * nm);
        atomicAdd(ad + i + 1, v1 * nm);
        atomicAdd(ad + i + 2, v2 * nm);
        atomicAdd(ad + i + 3, v3 * nm);
    }
}

// ---------------------------------------------------------------------------
__global__ void gcn_fin1(const float* __restrict__ agg,
                         const float* __restrict__ dinv,
                         const float* __restrict__ b,
                         float* __restrict__ h, int n) {
    int i = blockIdx.x * blockDim.x + threadIdx.x;
    if (i >= n * D_HID) return;
    int node = i / D_HID;
    int c    = i % D_HID;
    float di = dinv[node];
    float v  = agg[i] + di * di * h[i] + b[c];
    h[i] = v > 0.f ? v : 0.f;
}

__global__ void gcn_fin2(const float* __restrict__ agg,
                         const float* __restrict__ dinv,
                         const float* __restrict__ b,
                         const float* __restrict__ h,
                         float* __restrict__ out, int n) {
    int i = blockIdx.x * blockDim.x + threadIdx.x;
    if (i >= n * D_OUT) return;
    int node = i / D_OUT;
    int c    = i % D_OUT;
    float di = dinv[node];
    out[i] = agg[i] + di * di * h[i] + b[c];
}

// ---------------------------------------------------------------------------
extern "C" void kernel_launch(void* const* d_in, const int* in_sizes, int n_in,
                              void* d_out, int out_size) {
    const float* x  = (const float*)d_in[0];
    const void*  ei = d_in[1];                 // dtype detected on device
    const float* ew = (const float*)d_in[2];
    const float* W1 = (const float*)d_in[3];
    const float* b1 = (const float*)d_in[4];
    const float* W2 = (const float*)d_in[5];
    const float* b2 = (const float*)d_in[6];
    float*       out = (float*)d_out;

    int n = in_sizes[0] / D_IN;      // 100000
    int E = in_sizes[2];             // 1600000 (from edge_weight: float32 for sure)

    float *h1, *agg1, *h2, *agg2, *deg, *norm;
    int *src32, *dst32, *flag;
    cudaGetSymbolAddress((void**)&h1,    s_h1);
    cudaGetSymbolAddress((void**)&agg1,  s_agg1);
    cudaGetSymbolAddress((void**)&h2,    s_h2);
    cudaGetSymbolAddress((void**)&agg2,  s_agg2);
    cudaGetSymbolAddress((void**)&deg,   s_deg);
    cudaGetSymbolAddress((void**)&norm,  s_norm);
    cudaGetSymbolAddress((void**)&src32, s_src);
    cudaGetSymbolAddress((void**)&dst32, s_dst);
    cudaGetSymbolAddress((void**)&flag,  s_flag);

    // 0. detect index dtype
    gcn_detect<<<1, 32>>>((const unsigned*)ei, flag);

    // 1. zero scratch + index conversion (clamped)
    gcn_prep<<<2048, 256>>>(ei, flag, agg1, agg2, deg, src32, dst32, n, E);

    // 2. degrees, dinv, per-edge norms
    gcn_deg <<<(E + 255) / 256, 256>>>(dst32, ew, deg, E);
    gcn_dinv<<<(n + 255) / 256, 256>>>(deg, n);
    gcn_norm<<<(E + 255) / 256, 256>>>(src32, dst32, ew, deg, norm, E);

    // 3. GEMM1: h1 = x @ W1   (BM=64, BK=32, 4x6 microtile, 128 threads)
    gcn_gemm<D_IN, D_HID, 64, 32, 4, 6><<<(n + 63) / 64, 128>>>(x, W1, h1, n);

    // 4. edge scatter layer 1
    gcn_edge<D_HID><<<(E + 255) / 256, 256>>>(src32, dst32, norm, h1, agg1, E);

    // 5. finalize layer 1 (self-loop + bias + relu)
    gcn_fin1<<<(n * D_HID + 255) / 256, 256>>>(agg1, deg, b1, h1, n);

    // 6. GEMM2: h2 = h1 @ W2  (BM=64, BK=48 full, 4x4 microtile, 128 threads)
    gcn_gemm<D_HID, D_OUT, 64, 48, 4, 4><<<(n + 63) / 64, 128>>>(h1, W2, h2, n);

    // 7. edge scatter layer 2
    gcn_edge<D_OUT><<<(E + 255) / 256, 256>>>(src32, dst32, norm, h2, agg2, E);

    // 8. finalize layer 2 into output
    gcn_fin2<<<(n * D_OUT + 255) / 256, 256>>>(agg2, deg, b2, h2, out, n);
}

// round 5
// speedup vs baseline: 4.2396x; 4.2396x over previous
#include <cuda_runtime.h>
#include <cstdint>

#define D_IN  128
#define D_HID 48
#define D_OUT 32
#define MAX_N 100000
#define MAX_E 1600000
#define NB_MAX 512   // scan blocks (n/256 <= 512 -> n <= 131072)

// Scratch (module-static device memory — the sanctioned no-alloc pattern)
__device__ float s_h1 [MAX_N * D_HID];   // x@W1 (raw)
__device__ float s_a1 [MAX_N * D_HID];   // layer-1 activation (post agg+relu)
__device__ float s_h2 [MAX_N * D_OUT];   // a1@W2 (raw)
__device__ float s_deg[MAX_N];           // weighted degree -> dinv
__device__ int   s_cnt[MAX_N];           // in-degree counts
__device__ int   s_ex [MAX_N];           // per-block exclusive scan
__device__ int   s_row[MAX_N + 1];       // CSR rowptr
__device__ int   s_cur[MAX_N];           // build cursors
__device__ int   s_bsum[NB_MAX];         // block sums for scan
__device__ int   s_src[MAX_E];
__device__ int   s_dst[MAX_E];
__device__ int   s_col[MAX_E];           // CSR col (src node)
__device__ float s_val[MAX_E];           // CSR val = dinv[src]*ew
__device__ int   s_flag[1];              // 1 => edge_index delivered as int64

// ---------------------------------------------------------------------------
// Detect edge_index dtype (int64 => odd 32-bit words all zero)
// ---------------------------------------------------------------------------
__global__ void gcn_detect(const unsigned* __restrict__ ei_words,
                           int* __restrict__ flag) {
    if (threadIdx.x == 0 && blockIdx.x == 0) {
        int nz = 0;
        #pragma unroll 8
        for (int i = 1; i < 512; i += 2) nz += (ei_words[i] != 0u);
        flag[0] = (nz == 0) ? 1 : 0;
    }
}

// ---------------------------------------------------------------------------
// zero counters + convert indices to clamped int32
// ---------------------------------------------------------------------------
__global__ void gcn_prep(const void* __restrict__ ei_raw,
                         const int* __restrict__ flag,
                         float* __restrict__ deg, int* __restrict__ cnt,
                         int* __restrict__ src32, int* __restrict__ dst32,
                         int n, int E) {
    int stride = gridDim.x * blockDim.x;
    int tid0 = blockIdx.x * blockDim.x + threadIdx.x;
    for (int i = tid0; i < n; i += stride) { deg[i] = 0.f; cnt[i] = 0; }
    bool is64 = (flag[0] != 0);
    const long long* ei64 = (const long long*)ei_raw;
    const int*       ei32 = (const int*)ei_raw;
    for (int e = tid0; e < E; e += stride) {
        int sv, dv;
        if (is64) { sv = (int)ei64[e]; dv = (int)ei64[E + e]; }
        else      { sv = ei32[e];      dv = ei32[E + e]; }
        sv = min(max(sv, 0), n - 1);
        dv = min(max(dv, 0), n - 1);
        src32[e] = sv;
        dst32[e] = dv;
    }
}

// ---------------------------------------------------------------------------
// weighted degree + in-degree count
// ---------------------------------------------------------------------------
__global__ void gcn_deg(const int* __restrict__ dst32,
                        const float* __restrict__ ew,
                        float* __restrict__ deg, int* __restrict__ cnt, int E) {
    int e = blockIdx.x * blockDim.x + threadIdx.x;
    if (e < E) {
        int d = dst32[e];
        atomicAdd(deg + d, ew[e]);
        atomicAdd(cnt + d, 1);
    }
}

__global__ void gcn_dinv(float* __restrict__ deg, int n) {
    int i = blockIdx.x * blockDim.x + threadIdx.x;
    if (i < n) deg[i] = rsqrtf(deg[i] + 1.0f);   // self-loop weight 1
}

// ---------------------------------------------------------------------------
// 3-phase exclusive scan of cnt -> rowptr (+ cursor copy)
// ---------------------------------------------------------------------------
__global__ void scan_blocks(const int* __restrict__ cnt,
                            int* __restrict__ ex, int* __restrict__ bsum, int n) {
    __shared__ int sh[256];
    int i = blockIdx.x * 256 + threadIdx.x;
    int v = (i < n) ? cnt[i] : 0;
    sh[threadIdx.x] = v;
    __syncthreads();
    #pragma unroll
    for (int off = 1; off < 256; off <<= 1) {
        int t = (threadIdx.x >= off) ? sh[threadIdx.x - off] : 0;
        __syncthreads();
        sh[threadIdx.x] += t;
        __syncthreads();
    }
    if (i < n) ex[i] = sh[threadIdx.x] - v;          // exclusive within block
    if (threadIdx.x == 255) bsum[blockIdx.x] = sh[255];
}

__global__ void scan_bsums(int* __restrict__ bsum, int nb) {
    __shared__ int sh[NB_MAX];
    int v = (threadIdx.x < nb) ? bsum[threadIdx.x] : 0;
    sh[threadIdx.x] = v;
    __syncthreads();
    #pragma unroll
    for (int off = 1; off < NB_MAX; off <<= 1) {
        int t = (threadIdx.x >= off) ? sh[threadIdx.x - off] : 0;
        __syncthreads();
        sh[threadIdx.x] += t;
        __syncthreads();
    }
    if (threadIdx.x < nb) bsum[threadIdx.x] = sh[threadIdx.x] - v;  // exclusive
}

__global__ void scan_add(const int* __restrict__ ex, const int* __restrict__ bsum,
                         int* __restrict__ rowptr, int* __restrict__ cursor,
                         int n, int E) {
    int i = blockIdx.x * 256 + threadIdx.x;
    if (i < n) {
        int r = ex[i] + bsum[blockIdx.x];
        rowptr[i] = r;
        cursor[i] = r;
    }
    if (i == 0) rowptr[n] = E;
}

// ---------------------------------------------------------------------------
// CSR build: col = src, val = dinv[src]*ew  (dinv[dst] factored to epilogue)
// ---------------------------------------------------------------------------
__global__ void gcn_build(const int* __restrict__ src32,
                          const int* __restrict__ dst32,
                          const float* __restrict__ ew,
                          const float* __restrict__ dinv,
                          int* __restrict__ cursor,
                          int* __restrict__ col, float* __restrict__ val, int E) {
    int e = blockIdx.x * blockDim.x + threadIdx.x;
    if (e >= E) return;
    int d = dst32[e];
    int pos = atomicAdd(cursor + d, 1);
    int s = src32[e];
    col[pos] = s;
    val[pos] = dinv[s] * ew[e];
}

// ---------------------------------------------------------------------------
// K-tiled fp32 GEMM: H[n, DOUT] = X[n, DIN] @ W[DIN, DOUT]
// ---------------------------------------------------------------------------
template<int DIN, int DOUT, int BM, int BK, int TM, int TN>
__global__ void gcn_gemm(const float* __restrict__ X,
                         const float* __restrict__ W,
                         float* __restrict__ H, int n) {
    constexpr int RT = BM / TM;
    constexpr int CT = DOUT / TN;
    constexpr int NT = RT * CT;

    __shared__ float sXT[BK * (BM + 1)];
    __shared__ float sW [BK * DOUT];

    int tid  = threadIdx.x;
    int row0 = blockIdx.x * BM;
    int ti = tid / CT;
    int tj = tid % CT;

    float acc[TM][TN];
    #pragma unroll
    for (int i = 0; i < TM; i++)
        #pragma unroll
        for (int j = 0; j < TN; j++) acc[i][j] = 0.f;

    for (int k0 = 0; k0 < DIN; k0 += BK) {
        for (int i = tid; i < BM * BK; i += NT) {
            int r = i / BK, c = i % BK;
            float v = (row0 + r < n) ? X[(size_t)(row0 + r) * DIN + k0 + c] : 0.f;
            sXT[c * (BM + 1) + r] = v;
        }
        for (int i = tid; i < BK * DOUT; i += NT) {
            int kk = i / DOUT, c = i % DOUT;
            sW[kk * DOUT + c] = W[(size_t)(k0 + kk) * DOUT + c];
        }
        __syncthreads();

        #pragma unroll 4
        for (int kk = 0; kk < BK; kk++) {
            float xr[TM];
            #pragma unroll
            for (int i = 0; i < TM; i++) xr[i] = sXT[kk * (BM + 1) + ti * TM + i];
            #pragma unroll
            for (int j = 0; j < TN; j++) {
                float wv = sW[kk * DOUT + tj * TN + j];
                #pragma unroll
                for (int i = 0; i < TM; i++) acc[i][j] += xr[i] * wv;
            }
        }
        __syncthreads();
    }

    #pragma unroll
    for (int i = 0; i < TM; i++) {
        int r = row0 + ti * TM + i;
        if (r < n) {
            #pragma unroll
            for (int j = 0; j < TN; j++)
                H[(size_t)r * DOUT + tj * TN + j] = acc[i][j];
        }
    }
}

// ---------------------------------------------------------------------------
// CSR aggregation, warp per node, lanes = features. Fused epilogue:
//   out = dinv[v] * sum(val*h[col]) + dinv[v]^2 * h[v] + b   (+ optional relu)
// ---------------------------------------------------------------------------
template<int D, bool RELU>
__global__ void gcn_agg(const int* __restrict__ rowptr,
                        const int* __restrict__ col,
                        const float* __restrict__ val,
                        const float* __restrict__ h,
                        const float* __restrict__ dinv,
                        const float* __restrict__ b,
                        float* __restrict__ out, int n) {
    int warp = (blockIdx.x * blockDim.x + threadIdx.x) >> 5;
    int lane = threadIdx.x & 31;
    if (warp >= n) return;

    int r0 = rowptr[warp];
    int r1 = rowptr[warp + 1];

    float acc0 = 0.f, acc1 = 0.f;
    for (int idx = r0; idx < r1; idx++) {
        int   c = col[idx];          // broadcast load
        float w = val[idx];          // broadcast load
        const float* hc = h + (size_t)c * D;
        acc0 += w * hc[lane];
        if (D > 32) { if (lane < D - 32) acc1 += w * hc[32 + lane]; }
    }

    float di = dinv[warp];
    const float* hv = h + (size_t)warp * D;
    float* ov = out + (size_t)warp * D;

    float o0 = di * acc0 + di * di * hv[lane] + b[lane];
    if (RELU) o0 = fmaxf(o0, 0.f);
    ov[lane] = o0;
    if (D > 32 && lane < D - 32) {
        float o1 = di * acc1 + di * di * hv[32 + lane] + b[32 + lane];
        if (RELU) o1 = fmaxf(o1, 0.f);
        ov[32 + lane] = o1;
    }
}

// ---------------------------------------------------------------------------
extern "C" void kernel_launch(void* const* d_in, const int* in_sizes, int n_in,
                              void* d_out, int out_size) {
    const float* x  = (const float*)d_in[0];
    const void*  ei = d_in[1];
    const float* ew = (const float*)d_in[2];
    const float* W1 = (const float*)d_in[3];
    const float* b1 = (const float*)d_in[4];
    const float* W2 = (const float*)d_in[5];
    const float* b2 = (const float*)d_in[6];
    float*       out = (float*)d_out;

    int n = in_sizes[0] / D_IN;      // 100000
    int E = in_sizes[2];             // 1600000
    int nb = (n + 255) / 256;        // scan blocks (391)

    float *h1, *a1, *h2, *deg, *val;
    int *cnt, *ex, *row, *cur, *bsum, *src32, *dst32, *colp, *flag;
    cudaGetSymbolAddress((void**)&h1,    s_h1);
    cudaGetSymbolAddress((void**)&a1,    s_a1);
    cudaGetSymbolAddress((void**)&h2,    s_h2);
    cudaGetSymbolAddress((void**)&deg,   s_deg);
    cudaGetSymbolAddress((void**)&cnt,   s_cnt);
    cudaGetSymbolAddress((void**)&ex,    s_ex);
    cudaGetSymbolAddress((void**)&row,   s_row);
    cudaGetSymbolAddress((void**)&cur,   s_cur);
    cudaGetSymbolAddress((void**)&bsum,  s_bsum);
    cudaGetSymbolAddress((void**)&src32, s_src);
    cudaGetSymbolAddress((void**)&dst32, s_dst);
    cudaGetSymbolAddress((void**)&colp,  s_col);
    cudaGetSymbolAddress((void**)&val,   s_val);
    cudaGetSymbolAddress((void**)&flag,  s_flag);

    // 0. index dtype detect + conversion + counter zero
    gcn_detect<<<1, 32>>>((const unsigned*)ei, flag);
    gcn_prep<<<2048, 256>>>(ei, flag, deg, cnt, src32, dst32, n, E);

    // 1. degrees (weighted + counts), dinv
    gcn_deg <<<(E + 255) / 256, 256>>>(dst32, ew, deg, cnt, E);
    gcn_dinv<<<(n + 255) / 256, 256>>>(deg, n);

    // 2. rowptr = exclusive_scan(cnt); cursors
    scan_blocks<<<nb, 256>>>(cnt, ex, bsum, n);
    scan_bsums <<<1, NB_MAX>>>(bsum, nb);
    scan_add   <<<nb, 256>>>(ex, bsum, row, cur, n, E);

    // 3. CSR build (col, val = dinv[src]*ew)
    gcn_build<<<(E + 255) / 256, 256>>>(src32, dst32, ew, deg, cur, colp, val, E);

    // 4. GEMM1: h1 = x @ W1
    gcn_gemm<D_IN, D_HID, 64, 32, 4, 6><<<(n + 63) / 64, 128>>>(x, W1, h1, n);

    // 5. aggregate layer 1 (fused self-loop + bias + relu) -> a1
    gcn_agg<D_HID, true><<<(n + 7) / 8, 256>>>(row, colp, val, h1, deg, b1, a1, n);

    // 6. GEMM2: h2 = a1 @ W2
    gcn_gemm<D_HID, D_OUT, 64, 48, 4, 4><<<(n + 63) / 64, 128>>>(a1, W2, h2, n);

    // 7. aggregate layer 2 (fused self-loop + bias) -> out
    gcn_agg<D_OUT, false><<<(n + 7) / 8, 256>>>(row, colp, val, h2, deg, b2, out, n);
}